// round 11
// baseline (speedup 1.0000x reference)
#include <cuda_runtime.h>
#include <cuda_fp16.h>
#include <cstdint>

// ============================================================================
// PatchMerged: Haar-DWT2 + LayerNorm + Linear fused into one GEMM over RAW x.
// Hybrid execution: output cols 0..159 on tensor cores (tf32 m16n8k8 classic
// mma.sync), cols 160..191 on the FFMA pipe (full fp32), running concurrently
// in one CTA — classic HMMA leaves the fma pipe ~85% idle.
//
//   out[row, d] = rstd * (X @ Wf)[row, d] + (-rstd*mu) * S1[d] + S0[d]
//   mu  = 2 * (sum of 'a' samples) / 384          (Haar block is orthonormal)
//   var = (sum x^2 over all 384 raw samples)/384 - mu^2
// ============================================================================

#define NOUT 192
#define KTOT 384
#define NCHUNK 12
#define NT 160                 // tensor-core columns
#define NF 32                  // FFMA columns

// ---- dynamic SMEM layout (bytes) ----
#define A_STAGE  16384         // 128 rows x 128B (XOR 16B-granule swizzle)
#define BT_STAGE 20480         // 160 rows x 128B
#define SM_A0    0                       // 3 stages: 0, 16384, 32768
#define SM_BT    49152                   // 3 stages: 49152, 69632, 90112
#define SM_BF    110592                  // 384 x 128B = 49152
#define SM_RED   159744                  // float2 red[128][2] = 2048
#define SM_S1    161792                  // float[192]
#define SM_S0    162560
#define SM_RSTD  163328                  // float[128]
#define SM_ALPHA 163840
#define SM_TOTAL 164352

// ---- precomputed weights (recomputed every launch; deterministic) ----
__device__ __align__(16) float g_WfT[NOUT * KTOT];   // [d][k], k=c*4+pos, tf32-rounded (d<160 used)
__device__ __align__(16) float g_WfFMA[KTOT][NF];    // [k][d-160], full fp32
__device__ float g_S1[NOUT];
__device__ float g_S0[NOUT];

// ============================================================================
// helpers
// ============================================================================
__device__ __forceinline__ uint32_t s2u(const void* p) {
    uint32_t a;
    asm("{ .reg .u64 t; cvta.to.shared.u64 t, %1; cvt.u32.u64 %0, t; }"
        : "=r"(a) : "l"(p));
    return a;
}
__device__ __forceinline__ void cp_async8(uint32_t s, const void* g) {
    asm volatile("cp.async.ca.shared.global [%0], [%1], 8;" :: "r"(s), "l"(g));
}
__device__ __forceinline__ void cp_async16(uint32_t s, const void* g) {
    asm volatile("cp.async.ca.shared.global [%0], [%1], 16;" :: "r"(s), "l"(g));
}
__device__ __forceinline__ float tf32_rna(float x) {
    float y;
    asm("cvt.rna.tf32.f32 %0, %1;" : "=f"(y) : "f"(x));
    return y;
}
__device__ __forceinline__ uint32_t lds_u32(uint32_t a) {
    uint32_t v;
    asm volatile("ld.shared.b32 %0, [%1];" : "=r"(v) : "r"(a));
    return v;
}
__device__ __forceinline__ float lds_f32(uint32_t a) {
    float v;
    asm volatile("ld.shared.f32 %0, [%1];" : "=f"(v) : "r"(a));
    return v;
}
__device__ __forceinline__ float4 lds_f32x4(uint32_t a) {
    float4 v;
    asm volatile("ld.shared.v4.f32 {%0,%1,%2,%3}, [%4];"
                 : "=f"(v.x), "=f"(v.y), "=f"(v.z), "=f"(v.w) : "r"(a));
    return v;
}

#define MMA_TF32(d, a, b0r, b1r)                                            \
    asm volatile(                                                           \
        "mma.sync.aligned.m16n8k8.row.col.f32.tf32.tf32.f32 "               \
        "{%0,%1,%2,%3}, {%4,%5,%6,%7}, {%8,%9}, {%0,%1,%2,%3};"             \
        : "+f"((d)[0]), "+f"((d)[1]), "+f"((d)[2]), "+f"((d)[3])            \
        : "r"((a)[0]), "r"((a)[1]), "r"((a)[2]), "r"((a)[3]),               \
          "r"(b0r), "r"(b1r))

// ============================================================================
// Prep: fold Haar signs + norm_w into WfT (tensor cols, tf32) and WfFMA
// (FFMA cols, fp32, k-major); compute S1, S0.
// ============================================================================
__global__ void prep_wfold(const float* __restrict__ nw, const float* __restrict__ w) {
    int c = blockIdx.x;    // 0..95
    int d = threadIdx.x;   // 0..191
    float w0 = nw[0 * 96 + c] * w[(0 * 96 + c) * NOUT + d];
    float w1 = nw[1 * 96 + c] * w[(1 * 96 + c) * NOUT + d];
    float w2 = nw[2 * 96 + c] * w[(2 * 96 + c) * NOUT + d];
    float w3 = nw[3 * 96 + c] * w[(3 * 96 + c) * NOUT + d];
    float va = 0.5f * (w0 + w1 + w2 + w3);   // pos a (h0,w0)
    float vb = 0.5f * (w0 + w1 - w2 - w3);   // pos b (h0,w1)
    float vc = 0.5f * (w0 - w1 + w2 - w3);   // pos c (h1,w0)
    float vd = 0.5f * (w0 - w1 - w2 + w3);   // pos d (h1,w1)
    if (d < NT) {
        float* dst = &g_WfT[d * KTOT + c * 4];
        dst[0] = tf32_rna(va);
        dst[1] = tf32_rna(vb);
        dst[2] = tf32_rna(vc);
        dst[3] = tf32_rna(vd);
    } else {
        int df = d - NT;
        g_WfFMA[c * 4 + 0][df] = va;
        g_WfFMA[c * 4 + 1][df] = vb;
        g_WfFMA[c * 4 + 2][df] = vc;
        g_WfFMA[c * 4 + 3][df] = vd;
    }
}

__global__ void prep_s(const float* __restrict__ nw, const float* __restrict__ nb,
                       const float* __restrict__ w) {
    int d = threadIdx.x;
    float s1 = 0.f, s0 = 0.f;
    for (int j = 0; j < KTOT; j++) {
        float wv = w[j * NOUT + d];
        s1 += nw[j] * wv;
        s0 += nb[j] * wv;
    }
    g_S1[d] = s1;
    g_S0[d] = s0;
}

// ============================================================================
// Main kernel. CTA = (b, i): 128 rows x 192 cols, 384 threads.
// Warps 0-7: tensor, grid 2(M) x 4(N), warp tile 64x40 (4x5 m16n8k8 tiles).
// Warps 8-11: FFMA, cols 160..191; thread tile 4 rows x 8 cols (32 acc).
// ============================================================================
__global__ void __launch_bounds__(384, 1)
pm_main(const float* __restrict__ x, float* __restrict__ out) {
    extern __shared__ char smem[];
    uint32_t sb = s2u(smem);
    int tid = threadIdx.x, lane = tid & 31, wid = tid >> 5;
    int bx = blockIdx.x;
    int b = bx >> 7, i = bx & 127;
    const float* xb = x + (size_t)b * 96 * 65536 + (size_t)(2 * i) * 256;

    float* S1s = (float*)(smem + SM_S1);
    float* S0s = (float*)(smem + SM_S0);
    if (tid < NOUT) { S1s[tid] = g_S1[tid]; S0s[tid] = g_S0[tid]; }

    // ---- chunk loaders (A: threads 0-255, 8B pairs; BT: threads 256-383) ----
    auto loadChunk = [&](int kc, int stage) {
        if (tid < 256) {
            uint32_t base = sb + SM_A0 + (uint32_t)(stage * A_STAGE);
#pragma unroll
            for (int it = 0; it < 8; ++it) {
                int idx = it * 256 + tid;          // 0..2047
                int j = idx & 127;
                int qq = idx >> 7;                 // 0..15
                int cc = qq >> 1, h = qq & 1;
                const float* g = xb + (size_t)(kc * 8 + cc) * 65536 + h * 256 + 2 * j;
                uint32_t off = (uint32_t)(j * 128 + ((cc ^ (j & 7)) << 4) + h * 8);
                cp_async8(base + off, g);
            }
        } else {
            uint32_t base = sb + SM_BT + (uint32_t)(stage * BT_STAGE);
            const float* g0 = g_WfT + kc * 32;
            int t = tid - 256;
#pragma unroll
            for (int it = 0; it < 10; ++it) {
                int idx = it * 128 + t;            // 0..1279
                int d = idx >> 3, u = idx & 7;     // d < 160
                uint32_t off = (uint32_t)(d * 128 + ((u ^ (d & 7)) << 4));
                cp_async16(base + off, g0 + (size_t)d * KTOT + u * 4);
            }
        }
    };

    // ---- B-fma one-time preload (k-major, linear 128B rows) ----
#pragma unroll
    for (int it = 0; it < 8; ++it) {
        int idx = it * 384 + tid;                  // 0..3071
        int k = idx >> 3, g = idx & 7;
        cp_async16(sb + SM_BF + (uint32_t)(k * 128 + g * 16), &g_WfFMA[k][g * 4]);
    }
    loadChunk(0, 0);
    asm volatile("cp.async.commit_group;" ::: "memory");
    loadChunk(1, 1);
    asm volatile("cp.async.commit_group;" ::: "memory");

    // ---- tensor-warp setup ----
    int wm = wid & 1, wn = wid >> 1;               // valid for wid<8
    int q = lane >> 2, p = lane & 3;
    uint32_t offA[4], offB[5];
#pragma unroll
    for (int mt = 0; mt < 4; ++mt)
        offA[mt] = (uint32_t)((wm * 64 + mt * 16 + q) * 128 + p * 4);
#pragma unroll
    for (int nt = 0; nt < 5; ++nt)
        offB[nt] = (uint32_t)((wn * 40 + nt * 8 + q) * 128 + p * 4);

    float acc[4][5][4];
#pragma unroll
    for (int mt = 0; mt < 4; ++mt)
#pragma unroll
        for (int nt = 0; nt < 5; ++nt)
#pragma unroll
            for (int e = 0; e < 4; ++e) acc[mt][nt][e] = 0.f;

    // ---- FFMA-warp setup ----
    int u = tid - 256, rg = u >> 2, cg = u & 3;    // valid for tid>=256
    float accf[4][8];
#pragma unroll
    for (int rr = 0; rr < 4; ++rr)
#pragma unroll
        for (int e = 0; e < 8; ++e) accf[rr][e] = 0.f;

    // stats (tensor threads): row sr = tid>>1, channel half sh = tid&1
    float suma = 0.f, ssq = 0.f;
    int sr = tid >> 1, sh = tid & 1;

    // ============================== main loop ==============================
    for (int n = 0; n < NCHUNK; ++n) {
        if (n < NCHUNK - 1)
            asm volatile("cp.async.wait_group 1;" ::: "memory");
        else
            asm volatile("cp.async.wait_group 0;" ::: "memory");
        __syncthreads();   // chunk n visible; stage (n+2)%3 free of readers
        if (n + 2 < NCHUNK) {
            loadChunk(n + 2, (n + 2) % 3);
            asm volatile("cp.async.commit_group;" ::: "memory");
        }

        uint32_t abase = sb + SM_A0 + (uint32_t)((n % 3) * A_STAGE);

        if (wid < 8) {
            // ------- tensor path: 4 k8-steps + stats -------
            uint32_t bbase = sb + SM_BT + (uint32_t)((n % 3) * BT_STAGE);
#pragma unroll
            for (int uu = 0; uu < 4; ++uu) {
                int cc = sh * 4 + uu;
                uint32_t a = abase + (uint32_t)(sr * 128 + ((cc ^ (sr & 7)) << 4));
                float4 v = lds_f32x4(a);
                suma += v.x;
                ssq += v.x * v.x + v.y * v.y + v.z * v.z + v.w * v.w;
            }
#pragma unroll
            for (int ks = 0; ks < 4; ++ks) {
                uint32_t sw0 = (uint32_t)(((2 * ks) ^ q) << 4);
                uint32_t sw1 = (uint32_t)(((2 * ks + 1) ^ q) << 4);
                uint32_t bf[5][2];
#pragma unroll
                for (int nt = 0; nt < 5; ++nt) {
                    bf[nt][0] = lds_u32(bbase + offB[nt] + sw0);
                    bf[nt][1] = lds_u32(bbase + offB[nt] + sw1);
                }
                uint32_t af[4][4];
#pragma unroll
                for (int mt = 0; mt < 4; ++mt) {
                    float a0 = lds_f32(abase + offA[mt] + sw0);
                    float a1 = lds_f32(abase + offA[mt] + 1024 + sw0);
                    float a2 = lds_f32(abase + offA[mt] + sw1);
                    float a3 = lds_f32(abase + offA[mt] + 1024 + sw1);
                    af[mt][0] = __float_as_uint(tf32_rna(a0));
                    af[mt][1] = __float_as_uint(tf32_rna(a1));
                    af[mt][2] = __float_as_uint(tf32_rna(a2));
                    af[mt][3] = __float_as_uint(tf32_rna(a3));
                }
#pragma unroll
                for (int mt = 0; mt < 4; ++mt)
#pragma unroll
                    for (int nt = 0; nt < 5; ++nt)
                        MMA_TF32(acc[mt][nt], af[mt], bf[nt][0], bf[nt][1]);
            }
        } else {
            // ------- FFMA path: 32 k-values for 4 rows x 8 cols -------
            uint32_t bfb = sb + SM_BF + (uint32_t)(n * 32 * 128 + cg * 32);
#pragma unroll 1
            for (int g = 0; g < 8; ++g) {
                float a_[4][4];
#pragma unroll
                for (int rr = 0; rr < 4; ++rr) {
                    int row = 4 * rg + rr;
                    float4 v = lds_f32x4(abase + (uint32_t)(row * 128 + ((g ^ (row & 7)) << 4)));
                    a_[rr][0] = v.x; a_[rr][1] = v.y; a_[rr][2] = v.z; a_[rr][3] = v.w;
                }
#pragma unroll
                for (int kk = 0; kk < 4; ++kk) {
                    uint32_t ba = bfb + (uint32_t)((g * 4 + kk) * 128);
                    float4 b0 = lds_f32x4(ba);
                    float4 b1 = lds_f32x4(ba + 16);
#pragma unroll
                    for (int rr = 0; rr < 4; ++rr) {
                        float av = a_[rr][kk];
                        accf[rr][0] = fmaf(av, b0.x, accf[rr][0]);
                        accf[rr][1] = fmaf(av, b0.y, accf[rr][1]);
                        accf[rr][2] = fmaf(av, b0.z, accf[rr][2]);
                        accf[rr][3] = fmaf(av, b0.w, accf[rr][3]);
                        accf[rr][4] = fmaf(av, b1.x, accf[rr][4]);
                        accf[rr][5] = fmaf(av, b1.y, accf[rr][5]);
                        accf[rr][6] = fmaf(av, b1.z, accf[rr][6]);
                        accf[rr][7] = fmaf(av, b1.w, accf[rr][7]);
                    }
                }
            }
        }
    }

    // ---- LayerNorm stats reduction -> per-row rstd / alpha ----
    if (tid < 256)
        ((float2*)(smem + SM_RED))[sr * 2 + sh] = make_float2(suma, ssq);
    __syncthreads();
    if (tid < 128) {
        float2 p0 = ((float2*)(smem + SM_RED))[tid * 2 + 0];
        float2 p1 = ((float2*)(smem + SM_RED))[tid * 2 + 1];
        float sa = p0.x + p1.x;
        float sq = p0.y + p1.y;
        float mu = sa * (2.0f / 384.0f);
        float var = sq * (1.0f / 384.0f) - mu * mu;
        float rstd = rsqrtf(var + 1e-5f);
        ((float*)(smem + SM_RSTD))[tid] = rstd;
        ((float*)(smem + SM_ALPHA))[tid] = -rstd * mu;
    }
    __syncthreads();

    const float* rstd_s = (const float*)(smem + SM_RSTD);
    const float* alpha_s = (const float*)(smem + SM_ALPHA);
    float* outb = out + (size_t)bx * 128 * NOUT;

    if (wid < 8) {
        // ---- tensor epilogue: cols 0..159 ----
#pragma unroll
        for (int mt = 0; mt < 4; ++mt) {
            int r0 = wm * 64 + mt * 16 + q;
            int r1 = r0 + 8;
            float rs0 = rstd_s[r0], al0 = alpha_s[r0];
            float rs1 = rstd_s[r1], al1 = alpha_s[r1];
#pragma unroll
            for (int nt = 0; nt < 5; ++nt) {
                int c0 = wn * 40 + nt * 8 + 2 * p;
                float s1a = S1s[c0], s1b = S1s[c0 + 1];
                float s0a = S0s[c0], s0b = S0s[c0 + 1];
                float2 v0, v1;
                v0.x = fmaf(rs0, acc[mt][nt][0], fmaf(al0, s1a, s0a));
                v0.y = fmaf(rs0, acc[mt][nt][1], fmaf(al0, s1b, s0b));
                v1.x = fmaf(rs1, acc[mt][nt][2], fmaf(al1, s1a, s0a));
                v1.y = fmaf(rs1, acc[mt][nt][3], fmaf(al1, s1b, s0b));
                *(float2*)(outb + (size_t)r0 * NOUT + c0) = v0;
                *(float2*)(outb + (size_t)r1 * NOUT + c0) = v1;
            }
        }
    } else {
        // ---- FFMA epilogue: cols 160..191 ----
        int c0 = NT + cg * 8;
#pragma unroll
        for (int rr = 0; rr < 4; ++rr) {
            int r = 4 * rg + rr;
            float rs = rstd_s[r], al = alpha_s[r];
            float4 o0, o1;
            o0.x = fmaf(rs, accf[rr][0], fmaf(al, S1s[c0 + 0], S0s[c0 + 0]));
            o0.y = fmaf(rs, accf[rr][1], fmaf(al, S1s[c0 + 1], S0s[c0 + 1]));
            o0.z = fmaf(rs, accf[rr][2], fmaf(al, S1s[c0 + 2], S0s[c0 + 2]));
            o0.w = fmaf(rs, accf[rr][3], fmaf(al, S1s[c0 + 3], S0s[c0 + 3]));
            o1.x = fmaf(rs, accf[rr][4], fmaf(al, S1s[c0 + 4], S0s[c0 + 4]));
            o1.y = fmaf(rs, accf[rr][5], fmaf(al, S1s[c0 + 5], S0s[c0 + 5]));
            o1.z = fmaf(rs, accf[rr][6], fmaf(al, S1s[c0 + 6], S0s[c0 + 6]));
            o1.w = fmaf(rs, accf[rr][7], fmaf(al, S1s[c0 + 7], S0s[c0 + 7]));
            *(float4*)(outb + (size_t)r * NOUT + c0) = o0;
            *(float4*)(outb + (size_t)r * NOUT + c0 + 4) = o1;
        }
    }
}

// ============================================================================
// Launch
// ============================================================================
extern "C" void kernel_launch(void* const* d_in, const int* in_sizes, int n_in,
                              void* d_out, int out_size) {
    const float* x  = (const float*)d_in[0];   // [16, 96, 256, 256]
    const float* nw = (const float*)d_in[1];   // [384]
    const float* nb = (const float*)d_in[2];   // [384]
    const float* w  = (const float*)d_in[3];   // [384, 192]
    float* out = (float*)d_out;                // [16, 16384, 192]
    (void)in_sizes; (void)n_in; (void)out_size;

    prep_wfold<<<96, 192>>>(nw, w);
    prep_s<<<1, 192>>>(nw, nb, w);

    cudaFuncSetAttribute(pm_main, cudaFuncAttributeMaxDynamicSharedMemorySize,
                         SM_TOTAL);
    pm_main<<<2048, 384, SM_TOTAL>>>(x, out);
}

// round 13
// speedup vs baseline: 1.4913x; 1.4913x over previous
#include <cuda_runtime.h>
#include <cuda_fp16.h>
#include <cstdint>

// ============================================================================
// PatchMerged: Haar-DWT2 + LayerNorm + Linear fused into one tf32 GEMM over
// RAW x data using classic mma.sync m16n8k8 (harness targets base sm_103 PTX,
// so tcgen05 is unavailable). R9 structure (measured 315.5us, ~HW ceiling for
// the classic tensor path) with two overhead cuts:
//   - A operand passed as raw fp32 bits (HW truncates to tf32): removes 64
//     cvt instructions per warp per chunk from the shared fma/alu pipe.
//   - 3-stage cp.async ring with ONE __syncthreads per chunk (was two).
//
//   out[row, d] = rstd * (X @ Wf)[row, d] + (-rstd*mu) * S1[d] + S0[d]
//   mu  = 2 * (sum of 'a' samples) / 384          (Haar block is orthonormal)
//   var = (sum x^2 over all 384 raw samples)/384 - mu^2
// ============================================================================

#define NOUT 192
#define KTOT 384
#define NCHUNK 12

// ---- dynamic SMEM layout (bytes) ----
#define A_STAGE  16384          // 128 rows x 128B (16B-granule XOR swizzle)
#define B_STAGE  24576          // 192 rows x 128B
#define SM_A0    0                          // stages 0 / 16384 / 32768
#define SM_B0    49152                      // stages 49152 / 73728 / 98304
#define SM_RED   122880                     // float2 red[128][2] = 2048
#define SM_S1    124928                     // float[192]
#define SM_S0    125696                     // float[192]
#define SM_RSTD  126464                     // float[128]
#define SM_ALPHA 126976                     // float[128]
#define SM_TOTAL 127488

// ---- precomputed weights (recomputed every launch; deterministic) ----
__device__ __align__(16) float g_WfT[NOUT * KTOT];   // [d][k], k=c*4+pos, tf32-rna
__device__ float g_S1[NOUT];
__device__ float g_S0[NOUT];

// ============================================================================
// helpers
// ============================================================================
__device__ __forceinline__ uint32_t s2u(const void* p) {
    uint32_t a;
    asm("{ .reg .u64 t; cvta.to.shared.u64 t, %1; cvt.u32.u64 %0, t; }"
        : "=r"(a) : "l"(p));
    return a;
}
__device__ __forceinline__ void cp_async8(uint32_t s, const void* g) {
    asm volatile("cp.async.ca.shared.global [%0], [%1], 8;" :: "r"(s), "l"(g));
}
__device__ __forceinline__ void cp_async16(uint32_t s, const void* g) {
    asm volatile("cp.async.ca.shared.global [%0], [%1], 16;" :: "r"(s), "l"(g));
}
__device__ __forceinline__ float tf32_rna(float x) {
    float y;
    asm("cvt.rna.tf32.f32 %0, %1;" : "=f"(y) : "f"(x));
    return y;
}
__device__ __forceinline__ uint32_t lds_u32(uint32_t a) {
    uint32_t v;
    asm volatile("ld.shared.b32 %0, [%1];" : "=r"(v) : "r"(a));
    return v;
}
__device__ __forceinline__ float4 lds_f32x4(uint32_t a) {
    float4 v;
    asm volatile("ld.shared.v4.f32 {%0,%1,%2,%3}, [%4];"
                 : "=f"(v.x), "=f"(v.y), "=f"(v.z), "=f"(v.w) : "r"(a));
    return v;
}

#define MMA_TF32(d, a, b0r, b1r)                                            \
    asm volatile(                                                           \
        "mma.sync.aligned.m16n8k8.row.col.f32.tf32.tf32.f32 "               \
        "{%0,%1,%2,%3}, {%4,%5,%6,%7}, {%8,%9}, {%0,%1,%2,%3};"             \
        : "+f"((d)[0]), "+f"((d)[1]), "+f"((d)[2]), "+f"((d)[3])            \
        : "r"((a)[0]), "r"((a)[1]), "r"((a)[2]), "r"((a)[3]),               \
          "r"(b0r), "r"(b1r))

// ============================================================================
// Prep: fold Haar signs + norm_w into WfT (tf32-rna); compute S1, S0.
//   Wf[(c,p), d] = 0.5 * sum_q sign[q][p] * norm_w[q*96+c] * w_red[q*96+c, d]
//   S1[d] = sum_j norm_w[j]*w_red[j,d];  S0[d] = sum_j norm_b[j]*w_red[j,d]
// ============================================================================
__global__ void prep_wfold(const float* __restrict__ nw, const float* __restrict__ w) {
    int c = blockIdx.x;    // 0..95
    int d = threadIdx.x;   // 0..191
    float w0 = nw[0 * 96 + c] * w[(0 * 96 + c) * NOUT + d];
    float w1 = nw[1 * 96 + c] * w[(1 * 96 + c) * NOUT + d];
    float w2 = nw[2 * 96 + c] * w[(2 * 96 + c) * NOUT + d];
    float w3 = nw[3 * 96 + c] * w[(3 * 96 + c) * NOUT + d];
    float* dst = &g_WfT[d * KTOT + c * 4];
    dst[0] = tf32_rna(0.5f * (w0 + w1 + w2 + w3));   // pos a (h0,w0)
    dst[1] = tf32_rna(0.5f * (w0 + w1 - w2 - w3));   // pos b (h0,w1)
    dst[2] = tf32_rna(0.5f * (w0 - w1 + w2 - w3));   // pos c (h1,w0)
    dst[3] = tf32_rna(0.5f * (w0 - w1 - w2 + w3));   // pos d (h1,w1)
}

__global__ void prep_s(const float* __restrict__ nw, const float* __restrict__ nb,
                       const float* __restrict__ w) {
    int d = threadIdx.x;
    float s1 = 0.f, s0 = 0.f;
    for (int j = 0; j < KTOT; j++) {
        float wv = w[j * NOUT + d];
        s1 += nw[j] * wv;
        s0 += nb[j] * wv;
    }
    g_S1[d] = s1;
    g_S0[d] = s0;
}

// ============================================================================
// Main kernel. CTA = (b, i): 128 rows x 192 cols. 8 warps: 2(M) x 4(N),
// warp tile 64x48 = 4x6 m16n8k8 tiles, 96 fp32 accums/thread.
// ============================================================================
__global__ void __launch_bounds__(256)
pm_main(const float* __restrict__ x, float* __restrict__ out) {
    extern __shared__ char smem[];
    uint32_t sb = s2u(smem);
    int tid = threadIdx.x, lane = tid & 31, wid = tid >> 5;
    int wm = wid & 1, wn = wid >> 1;       // warp grid 2(M) x 4(N)
    int q = lane >> 2, p = lane & 3;       // quad row / thread-in-quad
    int bx = blockIdx.x;
    int b = bx >> 7, i = bx & 127;
    const float* xb = x + (size_t)b * 96 * 65536 + (size_t)(2 * i) * 256;

    float* S1s = (float*)(smem + SM_S1);
    float* S0s = (float*)(smem + SM_S0);
    if (tid < NOUT) { S1s[tid] = g_S1[tid]; S0s[tid] = g_S0[tid]; }

    // A loader: chunk kc covers channels 8kc..8kc+7. k-in-chunk = cc*4 + pos.
    // (a,b) pair = one 8B word at x[c,2i,2j]; (c,d) pair at x[c,2i+1,2j].
    // SMEM row j = 128B; 16B-granule XOR swizzle: granule g -> g ^ (j&7).
    auto loadChunk = [&](int kc, int stage) {
        uint32_t abase = sb + SM_A0 + (uint32_t)(stage * A_STAGE);
#pragma unroll
        for (int it = 0; it < 8; ++it) {
            int idx = it * 256 + tid;          // 0..2047
            int j = idx & 127;
            int qq = idx >> 7;                 // 0..15
            int cc = qq >> 1, h = qq & 1;
            const float* g = xb + (size_t)(kc * 8 + cc) * 65536 + h * 256 + 2 * j;
            uint32_t off = (uint32_t)(j * 128 + ((cc ^ (j & 7)) << 4) + h * 8);
            cp_async8(abase + off, g);
        }
        uint32_t bbase = sb + SM_B0 + (uint32_t)(stage * B_STAGE);
        const float* g0 = g_WfT + kc * 32;
#pragma unroll
        for (int it = 0; it < 6; ++it) {
            int idx = it * 256 + tid;          // 0..1535
            int d = idx >> 3, u = idx & 7;
            uint32_t off = (uint32_t)(d * 128 + ((u ^ (d & 7)) << 4));
            cp_async16(bbase + off, g0 + (size_t)d * KTOT + u * 4);
        }
    };

    loadChunk(0, 0);
    asm volatile("cp.async.commit_group;" ::: "memory");
    loadChunk(1, 1);
    asm volatile("cp.async.commit_group;" ::: "memory");

    float acc[4][6][4];
#pragma unroll
    for (int mt = 0; mt < 4; ++mt)
#pragma unroll
        for (int nt = 0; nt < 6; ++nt)
#pragma unroll
            for (int e = 0; e < 4; ++e) acc[mt][nt][e] = 0.f;

    // per-thread fragment base offsets (swizzle term added per k-step)
    uint32_t offA[4], offB[6];
#pragma unroll
    for (int mt = 0; mt < 4; ++mt)
        offA[mt] = (uint32_t)((wm * 64 + mt * 16 + q) * 128 + p * 4);
#pragma unroll
    for (int nt = 0; nt < 6; ++nt)
        offB[nt] = (uint32_t)((wn * 48 + nt * 8 + q) * 128 + p * 4);

    // stats: thread t handles row sr = t>>1, channel half sh = t&1
    float suma = 0.f, ssq = 0.f;
    int sr = tid >> 1, sh = tid & 1;

    for (int n = 0; n < NCHUNK; ++n) {
        if (n < NCHUNK - 1)
            asm volatile("cp.async.wait_group 1;" ::: "memory");   // chunk n landed
        else
            asm volatile("cp.async.wait_group 0;" ::: "memory");
        __syncthreads();   // chunk n visible; readers of stage (n+2)%3 are done
        if (n + 2 < NCHUNK) {
            loadChunk(n + 2, (n + 2) % 3);
            asm volatile("cp.async.commit_group;" ::: "memory");
        }

        uint32_t abase = sb + SM_A0 + (uint32_t)((n % 3) * A_STAGE);
        uint32_t bbase = sb + SM_B0 + (uint32_t)((n % 3) * B_STAGE);

        // ---- stats from landed A chunk (each 16B granule = one channel's abcd)
#pragma unroll
        for (int u = 0; u < 4; ++u) {
            int cc = sh * 4 + u;
            uint32_t a = abase + (uint32_t)(sr * 128 + ((cc ^ (sr & 7)) << 4));
            float4 v = lds_f32x4(a);
            suma += v.x;                                  // 'a' sample
            ssq += v.x * v.x + v.y * v.y + v.z * v.z + v.w * v.w;
        }

        // ---- 4 k8-steps of m16n8k8 tf32 mma (A = raw fp32 bits, HW-truncated)
#pragma unroll
        for (int ks = 0; ks < 4; ++ks) {
            uint32_t sw0 = (uint32_t)(((2 * ks) ^ q) << 4);      // k = 8ks + p
            uint32_t sw1 = (uint32_t)(((2 * ks + 1) ^ q) << 4);  // k = 8ks + 4 + p
            uint32_t bf[6][2];
#pragma unroll
            for (int nt = 0; nt < 6; ++nt) {
                bf[nt][0] = lds_u32(bbase + offB[nt] + sw0);
                bf[nt][1] = lds_u32(bbase + offB[nt] + sw1);
            }
            uint32_t af[4][4];
#pragma unroll
            for (int mt = 0; mt < 4; ++mt) {
                af[mt][0] = lds_u32(abase + offA[mt] + sw0);
                af[mt][1] = lds_u32(abase + offA[mt] + 1024 + sw0);   // row + 8
                af[mt][2] = lds_u32(abase + offA[mt] + sw1);
                af[mt][3] = lds_u32(abase + offA[mt] + 1024 + sw1);
            }
#pragma unroll
            for (int mt = 0; mt < 4; ++mt)
#pragma unroll
                for (int nt = 0; nt < 6; ++nt)
                    MMA_TF32(acc[mt][nt], af[mt], bf[nt][0], bf[nt][1]);
        }
    }

    // ---- LayerNorm stats reduction -> per-row rstd / alpha
    ((float2*)(smem + SM_RED))[sr * 2 + sh] = make_float2(suma, ssq);
    __syncthreads();
    if (tid < 128) {
        float2 p0 = ((float2*)(smem + SM_RED))[tid * 2 + 0];
        float2 p1 = ((float2*)(smem + SM_RED))[tid * 2 + 1];
        float sa = p0.x + p1.x;
        float sq = p0.y + p1.y;
        float mu = sa * (2.0f / 384.0f);
        float var = sq * (1.0f / 384.0f) - mu * mu;
        float rstd = rsqrtf(var + 1e-5f);
        ((float*)(smem + SM_RSTD))[tid] = rstd;
        ((float*)(smem + SM_ALPHA))[tid] = -rstd * mu;
    }
    __syncthreads();

    // ---- epilogue: affine + store (8B stores, 32B-sector aligned per quad)
    const float* rstd_s = (const float*)(smem + SM_RSTD);
    const float* alpha_s = (const float*)(smem + SM_ALPHA);
    float* outb = out + (size_t)bx * 128 * NOUT;
#pragma unroll
    for (int mt = 0; mt < 4; ++mt) {
        int r0 = wm * 64 + mt * 16 + q;
        int r1 = r0 + 8;
        float rs0 = rstd_s[r0], al0 = alpha_s[r0];
        float rs1 = rstd_s[r1], al1 = alpha_s[r1];
#pragma unroll
        for (int nt = 0; nt < 6; ++nt) {
            int c0 = wn * 48 + nt * 8 + 2 * p;
            float s1a = S1s[c0], s1b = S1s[c0 + 1];
            float s0a = S0s[c0], s0b = S0s[c0 + 1];
            float2 v0, v1;
            v0.x = fmaf(rs0, acc[mt][nt][0], fmaf(al0, s1a, s0a));
            v0.y = fmaf(rs0, acc[mt][nt][1], fmaf(al0, s1b, s0b));
            v1.x = fmaf(rs1, acc[mt][nt][2], fmaf(al1, s1a, s0a));
            v1.y = fmaf(rs1, acc[mt][nt][3], fmaf(al1, s1b, s0b));
            *(float2*)(outb + (size_t)r0 * NOUT + c0) = v0;
            *(float2*)(outb + (size_t)r1 * NOUT + c0) = v1;
        }
    }
}

// ============================================================================
// Launch
// ============================================================================
extern "C" void kernel_launch(void* const* d_in, const int* in_sizes, int n_in,
                              void* d_out, int out_size) {
    const float* x  = (const float*)d_in[0];   // [16, 96, 256, 256]
    const float* nw = (const float*)d_in[1];   // [384]
    const float* nb = (const float*)d_in[2];   // [384]
    const float* w  = (const float*)d_in[3];   // [384, 192]
    float* out = (float*)d_out;                // [16, 16384, 192]
    (void)in_sizes; (void)n_in; (void)out_size;

    prep_wfold<<<96, 192>>>(nw, w);
    prep_s<<<1, 192>>>(nw, nb, w);

    cudaFuncSetAttribute(pm_main, cudaFuncAttributeMaxDynamicSharedMemorySize,
                         SM_TOTAL);
    pm_main<<<2048, 256, SM_TOTAL>>>(x, out);
}